// round 6
// baseline (speedup 1.0000x reference)
#include <cuda_runtime.h>
#include <cstdint>
#include <math.h>

#define BB 1024
#define SS 64
#define EE 100
#define HH 512
#define VV 50000
#define EP 112            // padded E (multiple of 8, >= 100)

// ---------------------------------------------------------------------------
// Static device scratch (no allocations allowed)
// ---------------------------------------------------------------------------
__device__ float    g_h[2][3 * BB * HH];                 // fp32 hidden (blend path)
__device__ uint32_t g_htf[2][3 * BB * HH];               // tf32, K-permuted (GEMM A path)
__device__ float    g_eqc[BB * HH];
__device__ float    g_gi[(size_t)3 * BB * SS * 3 * HH];  // input projections, 1.2 GB
__device__ uint32_t g_whh_p[3 * 16 * 96 * HH];           // packed whh panels (tf32, perm K)
__device__ uint32_t g_wih_p[3 * 3 * HH * EP];            // packed wih (tf32, perm K, pad)
__device__ uint32_t g_emb_p[(size_t)3 * VV * EP];        // packed emb (tf32, perm K, pad)

struct Enc {
    const int*   tok;
    const float* emb;
    const float* wih;
    const float* whh;
    const float* bih;
    const float* bhh;
};
struct EncPack { Enc e[3]; };

__device__ __forceinline__ float sigmoidf_(float x) {
    return 1.0f / (1.0f + __expf(-x));
}

// ===========================================================================
// PTX helpers (sm_80-portable)
// ===========================================================================
__device__ __forceinline__ uint32_t smem_u32(const void* p) {
    uint32_t a;
    asm("{ .reg .u64 t; cvta.to.shared.u64 t, %1; cvt.u32.u64 %0, t; }" : "=r"(a) : "l"(p));
    return a;
}
__device__ __forceinline__ void cp16(uint32_t dst, const void* src) {
    asm volatile("cp.async.cg.shared.global [%0], [%1], 16;" :: "r"(dst), "l"(src));
}
#define CP_COMMIT() asm volatile("cp.async.commit_group;" ::: "memory")
#define CP_WAIT1()  asm volatile("cp.async.wait_group 1;" ::: "memory")

__device__ __forceinline__ uint32_t f2tf(float x) {
    uint32_t r;
    asm("cvt.rna.tf32.f32 %0, %1;" : "=r"(r) : "f"(x));
    return r;
}
__device__ __forceinline__ void mma8(float* d, const uint32_t* a, uint32_t b0, uint32_t b1) {
    asm volatile("mma.sync.aligned.m16n8k8.row.col.f32.tf32.tf32.f32 "
                 "{%0,%1,%2,%3}, {%4,%5,%6,%7}, {%8,%9}, {%0,%1,%2,%3};"
                 : "+f"(d[0]), "+f"(d[1]), "+f"(d[2]), "+f"(d[3])
                 : "r"(a[0]), "r"(a[1]), "r"(a[2]), "r"(a[3]), "r"(b0), "r"(b1));
}

// K-permutation within 8-groups: source col c -> position 2*(c&3) + ((c>>2)&1)
__device__ __forceinline__ int permk(int k) {
    return (k & ~7) | (((k & 3) << 1) | ((k >> 2) & 1));
}

// ===========================================================================
// Init + pack kernels
// ===========================================================================
__global__ void zero_h_kernel() {
    size_t i = (size_t)blockIdx.x * blockDim.x + threadIdx.x;
    if (i < (size_t)3 * BB * HH) { g_h[0][i] = 0.0f; g_htf[0][i] = 0u; }
}

// whh -> panels [e][jtile(16)][n(96)][K(512) perm], n = jg*24 + sec*8 + jj
__global__ void pack_whh_kernel(EncPack P) {
    int id = blockIdx.x * blockDim.x + threadIdx.x;
    if (id >= 3 * 16 * 96 * HH) return;
    int k = id & (HH - 1);
    int r = id >> 9;
    int n = r % 96; r /= 96;
    int jt = r % 16; int e = r / 16;
    int jg = n / 24, sec = (n % 24) >> 3, jj = n & 7;
    int j = jt * 32 + jg * 8 + jj;
    float v = P.e[e].whh[(size_t)(sec * HH + j) * HH + k];
    g_whh_p[(((size_t)(e * 16 + jt) * 96 + n) << 9) | permk(k)] = f2tf(v);
}

// wih -> [e][n(1536)][EP perm, zero-padded]
__global__ void pack_wih_kernel(EncPack P) {
    int id = blockIdx.x * blockDim.x + threadIdx.x;
    if (id >= 3 * 3 * HH * EP) return;
    int k = id % EP;
    int n = (id / EP) % (3 * HH);
    int e = id / (EP * 3 * HH);
    float v = (k < EE) ? P.e[e].wih[(size_t)n * EE + k] : 0.0f;
    g_wih_p[((size_t)e * 3 * HH + n) * EP + (k & ~7) + (permk(k) & 7)] = f2tf(v);
}

// emb -> [e][v][EP perm, zero-padded]
__global__ void pack_emb_kernel(EncPack P) {
    size_t id = (size_t)blockIdx.x * blockDim.x + threadIdx.x;
    if (id >= (size_t)3 * VV * EP) return;
    int k = (int)(id % EP);
    int v = (int)((id / EP) % VV);
    int e = (int)(id / ((size_t)EP * VV));
    float x = (k < EE) ? P.e[e].emb[(size_t)v * EE + k] : 0.0f;
    g_emb_p[((size_t)e * VV + v) * EP + (k & ~7) + (permk(k) & 7)] = f2tf(x);
}

// ===========================================================================
// gi GEMM: gi[e][rt][n] = emb_p[tok[rt]] @ wih_p[n]^T    (rt = b*S+t, n in [0,1536))
// CTA: M=128 x N=128, K=112 (7 chunks of 16). grid (12, 512, 3), block 256.
// ===========================================================================
#define GPAD 20
__global__ __launch_bounds__(256, 2) void gi_kernel(EncPack P) {
    __shared__ uint32_t As[2][128 * GPAD];
    __shared__ uint32_t Bs[2][128 * GPAD];
    __shared__ int stok[128];

    const int e  = blockIdx.z;
    const int n0 = blockIdx.x * 128;
    const int r0 = blockIdx.y * 128;

    const uint32_t* __restrict__ Ep = g_emb_p + (size_t)e * VV * EP;
    const uint32_t* __restrict__ Wp = g_wih_p + (size_t)e * 3 * HH * EP;

    const int tid = threadIdx.x;
    const int lane = tid & 31, wid = tid >> 5;
    const int gr = lane >> 2, tg = lane & 3;
    const int warp_m = wid & 3, warp_n = wid >> 2;

    const uint32_t sA = smem_u32(As), sB = smem_u32(Bs);

    if (tid < 128) stok[tid] = P.e[e].tok[r0 + tid];
    __syncthreads();

    float acc[2][8][4];
#pragma unroll
    for (int a = 0; a < 2; a++)
#pragma unroll
        for (int b = 0; b < 8; b++)
#pragma unroll
            for (int c = 0; c < 4; c++) acc[a][b][c] = 0.0f;

    auto load_chunk = [&](int c, int st) {
        const uint32_t aB = sA + (uint32_t)st * 128 * GPAD * 4;
        const uint32_t bB = sB + (uint32_t)st * 128 * GPAD * 4;
#pragma unroll
        for (int it = 0; it < 4; it++) {
            int idx = tid + it * 256;              // [0,1024)
            int row = idx >> 2, kq = idx & 3;
            if (idx < 512)
                cp16(aB + (uint32_t)(row * GPAD + kq * 4) * 4,
                     Ep + (size_t)stok[row] * EP + c * 16 + kq * 4);
            else if (idx < 1024) {
                row -= 128;
                cp16(bB + (uint32_t)(row * GPAD + kq * 4) * 4,
                     Wp + (size_t)(n0 + row) * EP + c * 16 + kq * 4);
            }
        }
    };

    load_chunk(0, 0);
    CP_COMMIT();

    for (int c = 0; c < 7; c++) {
        if (c + 1 < 7) load_chunk(c + 1, (c + 1) & 1);
        CP_COMMIT();
        CP_WAIT1();
        __syncthreads();
        const uint32_t* Ast = As[c & 1];
        const uint32_t* Bst = Bs[c & 1];
#pragma unroll
        for (int g = 0; g < 2; g++) {
            uint32_t a[2][4];
#pragma unroll
            for (int mt = 0; mt < 2; mt++) {
                int rb = warp_m * 32 + mt * 16 + gr;
                uint2 lo = *(const uint2*)&Ast[rb * GPAD + g * 8 + tg * 2];
                uint2 hi = *(const uint2*)&Ast[(rb + 8) * GPAD + g * 8 + tg * 2];
                a[mt][0] = lo.x; a[mt][2] = lo.y; a[mt][1] = hi.x; a[mt][3] = hi.y;
            }
#pragma unroll
            for (int ntl = 0; ntl < 8; ntl++) {
                int n = warp_n * 64 + ntl * 8 + gr;
                uint2 bb = *(const uint2*)&Bst[n * GPAD + g * 8 + tg * 2];
                mma8(acc[0][ntl], a[0], bb.x, bb.y);
                mma8(acc[1][ntl], a[1], bb.x, bb.y);
            }
        }
        __syncthreads();
    }

#pragma unroll
    for (int mt = 0; mt < 2; mt++) {
#pragma unroll
        for (int ntl = 0; ntl < 8; ntl++) {
            int rt = r0 + warp_m * 32 + mt * 16 + gr;
            int col = n0 + warp_n * 64 + ntl * 8 + tg * 2;
            float* dst = g_gi + ((size_t)e * BB * SS + rt) * (3 * HH) + col;
            *(float2*)dst = make_float2(acc[mt][ntl][0], acc[mt][ntl][1]);
            *(float2*)(dst + (size_t)8 * 3 * HH) = make_float2(acc[mt][ntl][2], acc[mt][ntl][3]);
        }
    }
}

// ===========================================================================
// Fused GRU step: acc = h @ whh^T (N=96 per CTA: per 8-j group [r|z|h_n]),
// gate math + gi in epilogue. K=512, 32 chunks of 16, cvt-free (pre-packed).
// grid (16, 8, 3), block 256 (warps 4m x 2n), occ 2.
// ===========================================================================
#define SPAD 20
__global__ __launch_bounds__(256, 2) void step_tc_kernel(EncPack P, int t, int p) {
    __shared__ uint32_t As[2][128 * SPAD];
    __shared__ uint32_t Bs[2][96 * SPAD];

    const int e  = blockIdx.z;
    const Enc ep = P.e[e];
    const int j0 = blockIdx.x * 32;
    const int b0 = blockIdx.y * 128;

    const uint32_t* __restrict__ hp   = g_htf[p]     + (size_t)e * BB * HH;
    const float*    __restrict__ hin  = g_h[p]       + (size_t)e * BB * HH;
    float*          __restrict__ hout = g_h[p ^ 1]   + (size_t)e * BB * HH;
    uint32_t*       __restrict__ hop  = g_htf[p ^ 1] + (size_t)e * BB * HH;
    const uint32_t* __restrict__ Bp   = g_whh_p + ((size_t)(e * 16 + blockIdx.x) * 96) * HH;

    const int tid = threadIdx.x;
    const int lane = tid & 31, wid = tid >> 5;
    const int gr = lane >> 2, tg = lane & 3;
    const int warp_m = wid & 3, warp_n = wid >> 2;

    const uint32_t sA = smem_u32(As), sB = smem_u32(Bs);

    float acc[2][2][3][4];     // [mt][jg_l][sec][dreg]
#pragma unroll
    for (int a = 0; a < 2; a++)
#pragma unroll
        for (int b = 0; b < 2; b++)
#pragma unroll
            for (int s = 0; s < 3; s++)
#pragma unroll
                for (int c = 0; c < 4; c++) acc[a][b][s][c] = 0.0f;

    auto load_chunk = [&](int c, int st) {
        const uint32_t aB = sA + (uint32_t)st * 128 * SPAD * 4;
        const uint32_t bB = sB + (uint32_t)st * 96 * SPAD * 4;
#pragma unroll
        for (int it = 0; it < 4; it++) {
            int idx = tid + it * 256;              // [0,896)
            if (idx < 512) {
                int row = idx >> 2, kq = idx & 3;
                cp16(aB + (uint32_t)(row * SPAD + kq * 4) * 4,
                     hp + (size_t)(b0 + row) * HH + c * 16 + kq * 4);
            } else if (idx < 896) {
                int r2 = idx - 512;
                int row = r2 >> 2, kq = r2 & 3;
                cp16(bB + (uint32_t)(row * SPAD + kq * 4) * 4,
                     Bp + (size_t)row * HH + c * 16 + kq * 4);
            }
        }
    };

    load_chunk(0, 0);
    CP_COMMIT();

    for (int c = 0; c < 32; c++) {
        if (c + 1 < 32) load_chunk(c + 1, (c + 1) & 1);
        CP_COMMIT();
        CP_WAIT1();
        __syncthreads();
        const uint32_t* Ast = As[c & 1];
        const uint32_t* Bst = Bs[c & 1];
#pragma unroll
        for (int g = 0; g < 2; g++) {
            uint32_t a[2][4];
#pragma unroll
            for (int mt = 0; mt < 2; mt++) {
                int rb = warp_m * 32 + mt * 16 + gr;
                uint2 lo = *(const uint2*)&Ast[rb * SPAD + g * 8 + tg * 2];
                uint2 hi = *(const uint2*)&Ast[(rb + 8) * SPAD + g * 8 + tg * 2];
                a[mt][0] = lo.x; a[mt][2] = lo.y; a[mt][1] = hi.x; a[mt][3] = hi.y;
            }
#pragma unroll
            for (int ntl = 0; ntl < 6; ntl++) {
                int n = warp_n * 48 + ntl * 8 + gr;
                uint2 bb = *(const uint2*)&Bst[n * SPAD + g * 8 + tg * 2];
                int jg_l = ntl / 3, sec = ntl % 3;
                mma8(acc[0][jg_l][sec], a[0], bb.x, bb.y);
                mma8(acc[1][jg_l][sec], a[1], bb.x, bb.y);
            }
        }
        __syncthreads();
    }

    // ---- GRU epilogue ----
    float br[2][2], bz[2][2], bnh[2][2], bni[2][2];
#pragma unroll
    for (int jg_l = 0; jg_l < 2; jg_l++)
#pragma unroll
        for (int cc = 0; cc < 2; cc++) {
            int j = j0 + (warp_n * 2 + jg_l) * 8 + tg * 2 + cc;
            br[jg_l][cc]  = ep.bih[j]          + ep.bhh[j];
            bz[jg_l][cc]  = ep.bih[HH + j]     + ep.bhh[HH + j];
            bnh[jg_l][cc] = ep.bhh[2 * HH + j];
            bni[jg_l][cc] = ep.bih[2 * HH + j];
        }

#pragma unroll
    for (int mt = 0; mt < 2; mt++) {
#pragma unroll
        for (int rp = 0; rp < 2; rp++) {
            const int row = b0 + warp_m * 32 + mt * 16 + gr + rp * 8;
            const float* gir = g_gi + ((size_t)e * BB * SS + (size_t)row * SS + t) * (3 * HH);
            const float* hrow = hin + (size_t)row * HH;
            float*       orow = hout + (size_t)row * HH;
            uint32_t*    oprow = hop + (size_t)row * HH;
#pragma unroll
            for (int jg_l = 0; jg_l < 2; jg_l++) {
#pragma unroll
                for (int cc = 0; cc < 2; cc++) {
                    const int j = j0 + (warp_n * 2 + jg_l) * 8 + tg * 2 + cc;
                    const int k = rp * 2 + cc;
                    float r = sigmoidf_(gir[j] + acc[mt][jg_l][0][k] + br[jg_l][cc]);
                    float z = sigmoidf_(gir[HH + j] + acc[mt][jg_l][1][k] + bz[jg_l][cc]);
                    float n = tanhf(gir[2 * HH + j] + bni[jg_l][cc] +
                                    r * (acc[mt][jg_l][2][k] + bnh[jg_l][cc]));
                    float hv = (1.0f - z) * n + z * hrow[j];
                    orow[j] = hv;
                    oprow[(j & ~7) | (((j & 3) << 1) | ((j >> 2) & 1))] = f2tf(hv);
                }
            }
        }
    }
}

// ===========================================================================
// eqc = ((eq + ec) * 0.5) @ lin_w^T + lin_b
// ===========================================================================
__global__ __launch_bounds__(128) void eqc_kernel(const float* __restrict__ lin_w,
                                                  const float* __restrict__ lin_b,
                                                  int p) {
    const float* __restrict__ hq = g_h[p];
    const float* __restrict__ hc = g_h[p] + (size_t)BB * HH;
    const int n0 = blockIdx.x * 64;
    const int b0 = blockIdx.y * 64;

    __shared__ float As[16][65];
    __shared__ float Bs[16][65];

    const int tid = threadIdx.x;
    const int tx = tid & 15, ty = tid >> 4;

    float acc[8][4];
#pragma unroll
    for (int i = 0; i < 8; i++)
#pragma unroll
        for (int j = 0; j < 4; j++) acc[i][j] = 0.0f;

    for (int k0 = 0; k0 < HH; k0 += 16) {
#pragma unroll
        for (int l = 0; l < 8; l++) {
            int idx = tid + l * 128;
            int k = idx & 15, i = idx >> 4;
            size_t ga = (size_t)(b0 + i) * HH + (k0 + k);
            As[k][i] = 0.5f * (hq[ga] + hc[ga]);
            Bs[k][i] = lin_w[(size_t)(n0 + i) * HH + (k0 + k)];
        }
        __syncthreads();
#pragma unroll
        for (int k = 0; k < 16; k++) {
            float a[8], b[4];
#pragma unroll
            for (int i = 0; i < 8; i++) a[i] = As[k][ty * 8 + i];
#pragma unroll
            for (int j = 0; j < 4; j++) b[j] = Bs[k][tx * 4 + j];
#pragma unroll
            for (int i = 0; i < 8; i++)
#pragma unroll
                for (int j = 0; j < 4; j++) acc[i][j] += a[i] * b[j];
        }
        __syncthreads();
    }

    float bi[4];
#pragma unroll
    for (int j = 0; j < 4; j++) bi[j] = lin_b[n0 + tx * 4 + j];
#pragma unroll
    for (int i = 0; i < 8; i++) {
        size_t base = (size_t)(b0 + ty * 8 + i) * HH + n0 + tx * 4;
#pragma unroll
        for (int j = 0; j < 4; j++) g_eqc[base + j] = acc[i][j] + bi[j];
    }
}

// ===========================================================================
// logits[m] = X_m @ er^T, writes d_out
// ===========================================================================
__global__ __launch_bounds__(128) void logits_kernel(float* __restrict__ out, int p) {
    const int m = blockIdx.z;
    const float* __restrict__ X  = (m == 0) ? g_h[p]
                                 : (m == 1) ? g_h[p] + (size_t)BB * HH
                                            : g_eqc;
    const float* __restrict__ er = g_h[p] + (size_t)2 * BB * HH;
    const int n0 = blockIdx.x * 64;
    const int b0 = blockIdx.y * 64;

    __shared__ float As[16][65];
    __shared__ float Bs[16][65];

    const int tid = threadIdx.x;
    const int tx = tid & 15, ty = tid >> 4;

    float acc[8][4];
#pragma unroll
    for (int i = 0; i < 8; i++)
#pragma unroll
        for (int j = 0; j < 4; j++) acc[i][j] = 0.0f;

    for (int k0 = 0; k0 < HH; k0 += 16) {
#pragma unroll
        for (int l = 0; l < 8; l++) {
            int idx = tid + l * 128;
            int k = idx & 15, i = idx >> 4;
            As[k][i] = X[(size_t)(b0 + i) * HH + (k0 + k)];
            Bs[k][i] = er[(size_t)(n0 + i) * HH + (k0 + k)];
        }
        __syncthreads();
#pragma unroll
        for (int k = 0; k < 16; k++) {
            float a[8], b[4];
#pragma unroll
            for (int i = 0; i < 8; i++) a[i] = As[k][ty * 8 + i];
#pragma unroll
            for (int j = 0; j < 4; j++) b[j] = Bs[k][tx * 4 + j];
#pragma unroll
            for (int i = 0; i < 8; i++)
#pragma unroll
                for (int j = 0; j < 4; j++) acc[i][j] += a[i] * b[j];
        }
        __syncthreads();
    }

#pragma unroll
    for (int i = 0; i < 8; i++) {
        size_t base = (size_t)m * BB * BB + (size_t)(b0 + ty * 8 + i) * BB + n0 + tx * 4;
#pragma unroll
        for (int j = 0; j < 4; j++) out[base + j] = acc[i][j];
    }
}

// ===========================================================================
// Row softmax over 3*B rows of length B, in-place on d_out.
// ===========================================================================
__global__ __launch_bounds__(256) void softmax_kernel(float* __restrict__ out) {
    float* prow = out + (size_t)blockIdx.x * BB;
    __shared__ float red[256];
    const int tid = threadIdx.x;

    float v[4];
    float mx = -1e30f;
#pragma unroll
    for (int l = 0; l < 4; l++) {
        v[l] = prow[tid + l * 256];
        mx = fmaxf(mx, v[l]);
    }
    red[tid] = mx;
    __syncthreads();
    for (int s = 128; s > 0; s >>= 1) {
        if (tid < s) red[tid] = fmaxf(red[tid], red[tid + s]);
        __syncthreads();
    }
    mx = red[0];
    __syncthreads();

    float sum = 0.0f;
#pragma unroll
    for (int l = 0; l < 4; l++) {
        v[l] = __expf(v[l] - mx);
        sum += v[l];
    }
    red[tid] = sum;
    __syncthreads();
    for (int s = 128; s > 0; s >>= 1) {
        if (tid < s) red[tid] += red[tid + s];
        __syncthreads();
    }
    float inv = 1.0f / red[0];
#pragma unroll
    for (int l = 0; l < 4; l++) prow[tid + l * 256] = v[l] * inv;
}

// ===========================================================================
// Launch
// ===========================================================================
extern "C" void kernel_launch(void* const* d_in, const int* in_sizes, int n_in,
                              void* d_out, int out_size) {
    (void)in_sizes; (void)n_in; (void)out_size;

    EncPack P;
    const int* toks[3] = { (const int*)d_in[0], (const int*)d_in[1], (const int*)d_in[2] };
    for (int e = 0; e < 3; e++) {
        int b = 3 + e * 5;
        P.e[e].tok = toks[e];
        P.e[e].emb = (const float*)d_in[b + 0];
        P.e[e].wih = (const float*)d_in[b + 1];
        P.e[e].whh = (const float*)d_in[b + 2];
        P.e[e].bih = (const float*)d_in[b + 3];
        P.e[e].bhh = (const float*)d_in[b + 4];
    }
    const float* lin_w = (const float*)d_in[18];
    const float* lin_b = (const float*)d_in[19];
    float* out = (float*)d_out;

    zero_h_kernel<<<(3 * BB * HH + 255) / 256, 256>>>();
    pack_whh_kernel<<<(3 * 16 * 96 * HH + 255) / 256, 256>>>(P);
    pack_wih_kernel<<<(3 * 3 * HH * EP + 255) / 256, 256>>>(P);
    {
        size_t n = (size_t)3 * VV * EP;
        pack_emb_kernel<<<(unsigned)((n + 255) / 256), 256>>>(P);
    }

    gi_kernel<<<dim3(3 * HH / 128, BB * SS / 128, 3), 256>>>(P);

    int p = 0;
    for (int t = SS - 1; t >= 0; --t) {
        step_tc_kernel<<<dim3(HH / 32, BB / 128, 3), 256>>>(P, t, p);
        p ^= 1;
    }

    eqc_kernel<<<dim3(HH / 64, BB / 64), 128>>>(lin_w, lin_b, p);
    logits_kernel<<<dim3(BB / 64, BB / 64, 3), 128>>>(out, p);
    softmax_kernel<<<3 * BB, 256>>>(out);
}

// round 7
// speedup vs baseline: 1.5681x; 1.5681x over previous
#include <cuda_runtime.h>
#include <cstdint>
#include <math.h>

#define BB 1024
#define SS 64
#define EE 100
#define HH 512
#define VV 50000

// ---------------------------------------------------------------------------
// Static device scratch (no allocations allowed)
// g_h: hidden state, values tf32-pre-rounded, K-PERMUTED within 8-groups.
// ---------------------------------------------------------------------------
__device__ float    g_h[2][3 * BB * HH];
__device__ float    g_eqc[BB * HH];
__device__ uint32_t g_wpk[(size_t)3 * 16 * 128 * 640];   // packed W panels, 15.7 MB
__device__ uint32_t g_embp[(size_t)3 * VV * 128];        // packed emb, 76.8 MB

struct Enc {
    const int*   tok;
    const float* emb;
    const float* wih;
    const float* whh;
    const float* bih;
    const float* bhh;
};
struct EncPack { Enc e[3]; };

__device__ __forceinline__ float sigmoidf_(float x) {
    return 1.0f / (1.0f + __expf(-x));
}

// ===========================================================================
// PTX helpers (sm_80-portable)
// ===========================================================================
__device__ __forceinline__ void cp16(uint32_t dst, const void* src) {
    asm volatile("cp.async.cg.shared.global [%0], [%1], 16;" :: "r"(dst), "l"(src));
}
#define CP_COMMIT() asm volatile("cp.async.commit_group;" ::: "memory")
#define CP_WAIT1()  asm volatile("cp.async.wait_group 1;" ::: "memory")

__device__ __forceinline__ uint32_t smem_u32(const void* p) {
    uint32_t a;
    asm("{ .reg .u64 t; cvta.to.shared.u64 t, %1; cvt.u32.u64 %0, t; }" : "=r"(a) : "l"(p));
    return a;
}
__device__ __forceinline__ uint32_t f2tf(float x) {
    uint32_t r;
    asm("cvt.rna.tf32.f32 %0, %1;" : "=r"(r) : "f"(x));
    return r;
}
__device__ __forceinline__ void mma8(float* d, const uint32_t* a, uint32_t b0, uint32_t b1) {
    asm volatile("mma.sync.aligned.m16n8k8.row.col.f32.tf32.tf32.f32 "
                 "{%0,%1,%2,%3}, {%4,%5,%6,%7}, {%8,%9}, {%0,%1,%2,%3};"
                 : "+f"(d[0]), "+f"(d[1]), "+f"(d[2]), "+f"(d[3])
                 : "r"(a[0]), "r"(a[1]), "r"(a[2]), "r"(a[3]), "r"(b0), "r"(b1));
}

// K-permutation within 8-groups: source k -> position 2*(k&3) + ((k>>2)&1)
__device__ __forceinline__ int p8(int k)   { return ((k & 3) << 1) | ((k >> 2) & 1); }
// inverse: position p -> source k
__device__ __forceinline__ int ip8(int p)  { return ((p >> 1) & 3) | ((p & 1) << 2); }

// ===========================================================================
// Init + pack kernels
// ===========================================================================
__global__ void zero_h_kernel() {
    size_t i = (size_t)blockIdx.x * blockDim.x + threadIdx.x;
    if (i < (size_t)3 * BB * HH) g_h[0][i] = 0.0f;
}

// W panels: [e][jt(16)][n(128)][k(640), permuted].  n-tile nt=n>>3: jg=nt>>2,
// sec=nt&3, j=jt*32+jg*8+(n&7).  k<512: h-part (sec0..2=whh_r/z/n, sec3=0);
// k>=512: x-part kx=k-512 (sec0/1=wih_r/z, sec2=0, sec3=wih_n; kx>=100 -> 0).
__global__ void pack_w_kernel(EncPack P) {
    size_t id = (size_t)blockIdx.x * blockDim.x + threadIdx.x;
    if (id >= (size_t)3 * 16 * 128 * 640) return;
    int k  = (int)(id % 640);
    int n  = (int)((id / 640) % 128);
    int jt = (int)((id / (640 * 128)) % 16);
    int e  = (int)(id / (640 * 128 * 16));
    int nt = n >> 3, jg = nt >> 2, sec = nt & 3, jj = n & 7;
    int j = jt * 32 + jg * 8 + jj;
    float v = 0.0f;
    if (k < 512) {
        if (sec < 3) v = P.e[e].whh[(size_t)(sec * HH + j) * HH + k];
    } else {
        int kx = k - 512;
        if (kx < EE) {
            if (sec < 2)       v = P.e[e].wih[(size_t)(sec * HH + j) * EE + kx];
            else if (sec == 3) v = P.e[e].wih[(size_t)(2 * HH + j) * EE + kx];
        }
    }
    size_t dst = (((size_t)(e * 16 + jt) * 128 + n) * 640) + (k & ~7) + p8(k & 7);
    g_wpk[dst] = f2tf(v);
}

// emb: [e][v][k(128), permuted, zero-padded past E=100]
__global__ void pack_emb_kernel(EncPack P) {
    size_t id = (size_t)blockIdx.x * blockDim.x + threadIdx.x;
    if (id >= (size_t)3 * VV * 128) return;
    int k = (int)(id & 127);
    int v = (int)((id >> 7) % VV);
    int e = (int)(id / ((size_t)VV * 128));
    float x = (k < EE) ? P.e[e].emb[(size_t)v * EE + k] : 0.0f;
    g_embp[((size_t)e * VV + v) * 128 + (k & ~7) + p8(k & 7)] = f2tf(x);
}

// ===========================================================================
// Fused GRU step on tensor cores.  M=128 x N=128 x K=640 (40 chunks of 16).
// N sections per 8-j group: [r | z | h_n | i_n].  Inner loop: zero cvt,
// all fragment loads are LDS.64 from K-permuted tf32 data.
// grid (16, 8, 3), block 256 (warps 4m x 2n), 2 CTAs/SM.
// ===========================================================================
#define PAD  20
#define NCHK 40

__global__ __launch_bounds__(256, 2) void step_tc_kernel(EncPack P, int t, int p) {
    __shared__ uint32_t As[2][128 * PAD];
    __shared__ uint32_t Bs[2][128 * PAD];
    __shared__ int stok[128];

    const int e  = blockIdx.z;
    const Enc ep = P.e[e];
    const int jt = blockIdx.x;
    const int j0 = jt * 32;
    const int b0 = blockIdx.y * 128;

    const float* __restrict__ hin  = g_h[p]     + (size_t)e * BB * HH;
    float*       __restrict__ hout = g_h[p ^ 1] + (size_t)e * BB * HH;
    const uint32_t* __restrict__ Wp   = g_wpk  + ((size_t)(e * 16 + jt) * 128) * 640;
    const uint32_t* __restrict__ embp = g_embp + (size_t)e * VV * 128;

    const int tid = threadIdx.x;
    const int lane = tid & 31, wid = tid >> 5;
    const int gr = lane >> 2, tg = lane & 3;
    const int warp_m = wid & 3, warp_n = wid >> 2;

    const uint32_t sA = smem_u32(As), sB = smem_u32(Bs);

    if (tid < 128) stok[tid] = ep.tok[(b0 + tid) * SS + t];
    __syncthreads();

    float acc[2][2][4][4];           // [mt][jg_l][sec][dreg]
#pragma unroll
    for (int a = 0; a < 2; a++)
#pragma unroll
        for (int b = 0; b < 2; b++)
#pragma unroll
            for (int s = 0; s < 4; s++)
#pragma unroll
                for (int c = 0; c < 4; c++) acc[a][b][s][c] = 0.0f;

    auto load_chunk = [&](int c, int st) {
        const uint32_t aB = sA + (uint32_t)st * 128 * PAD * 4;
        const uint32_t bB = sB + (uint32_t)st * 128 * PAD * 4;
#pragma unroll
        for (int it = 0; it < 4; it++) {
            int idx = tid + it * 256;            // [0,1024)
            if (idx < 512) {
                int row = idx >> 2, kq = idx & 3;
                const void* src = (c < 32)
                    ? (const void*)(hin + (size_t)(b0 + row) * HH + c * 16 + kq * 4)
                    : (const void*)(embp + (size_t)stok[row] * 128 + (c - 32) * 16 + kq * 4);
                cp16(aB + (uint32_t)(row * PAD + kq * 4) * 4, src);
            } else {
                int r2 = idx - 512;
                int row = r2 >> 2, kq = r2 & 3;
                cp16(bB + (uint32_t)(row * PAD + kq * 4) * 4,
                     Wp + (size_t)row * 640 + c * 16 + kq * 4);
            }
        }
    };

    load_chunk(0, 0);
    CP_COMMIT();

    for (int c = 0; c < NCHK; c++) {
        if (c + 1 < NCHK) load_chunk(c + 1, (c + 1) & 1);
        CP_COMMIT();
        CP_WAIT1();
        __syncthreads();
        const uint32_t* Ast = As[c & 1];
        const uint32_t* Bst = Bs[c & 1];
#pragma unroll
        for (int g = 0; g < 2; g++) {
            uint32_t a[2][4];
#pragma unroll
            for (int mt = 0; mt < 2; mt++) {
                int rb = warp_m * 32 + mt * 16 + gr;
                uint2 lo = *(const uint2*)&Ast[rb * PAD + g * 8 + tg * 2];
                uint2 hi = *(const uint2*)&Ast[(rb + 8) * PAD + g * 8 + tg * 2];
                a[mt][0] = lo.x; a[mt][2] = lo.y; a[mt][1] = hi.x; a[mt][3] = hi.y;
            }
#pragma unroll
            for (int ntl = 0; ntl < 8; ntl++) {
                int n = warp_n * 64 + ntl * 8 + gr;
                uint2 bb = *(const uint2*)&Bst[n * PAD + g * 8 + tg * 2];
                int jg_l = ntl >> 2, sec = ntl & 3;
                mma8(acc[0][jg_l][sec], a[0], bb.x, bb.y);
                mma8(acc[1][jg_l][sec], a[1], bb.x, bb.y);
            }
        }
        __syncthreads();
    }

    // ---- GRU epilogue (per-thread, in-register) ----
    float br[2][2], bz[2][2], bnh[2][2], bni[2][2];
    int   jp[2][2];
#pragma unroll
    for (int jg_l = 0; jg_l < 2; jg_l++)
#pragma unroll
        for (int cc = 0; cc < 2; cc++) {
            int j = j0 + (warp_n * 2 + jg_l) * 8 + tg * 2 + cc;
            br[jg_l][cc]  = ep.bih[j]          + ep.bhh[j];
            bz[jg_l][cc]  = ep.bih[HH + j]     + ep.bhh[HH + j];
            bnh[jg_l][cc] = ep.bhh[2 * HH + j];
            bni[jg_l][cc] = ep.bih[2 * HH + j];
            jp[jg_l][cc]  = (j & ~7) | p8(j & 7);      // permuted storage pos
        }

#pragma unroll
    for (int mt = 0; mt < 2; mt++) {
#pragma unroll
        for (int rp = 0; rp < 2; rp++) {
            const int row = b0 + warp_m * 32 + mt * 16 + gr + rp * 8;
            const float* hrow = hin + (size_t)row * HH;
            float*       orow = hout + (size_t)row * HH;
#pragma unroll
            for (int jg_l = 0; jg_l < 2; jg_l++) {
#pragma unroll
                for (int cc = 0; cc < 2; cc++) {
                    const int k = rp * 2 + cc;
                    float r = sigmoidf_(acc[mt][jg_l][0][k] + br[jg_l][cc]);
                    float z = sigmoidf_(acc[mt][jg_l][1][k] + bz[jg_l][cc]);
                    float n = tanhf(acc[mt][jg_l][3][k] + bni[jg_l][cc] +
                                    r * (acc[mt][jg_l][2][k] + bnh[jg_l][cc]));
                    float hv = (1.0f - z) * n + z * hrow[jp[jg_l][cc]];
                    orow[jp[jg_l][cc]] = __uint_as_float(f2tf(hv));
                }
            }
        }
    }
}

// ===========================================================================
// eqc = ((eq + ec) * 0.5) @ lin_w^T + lin_b.  h is K-permuted in storage:
// lin_w is read through the inverse permutation; output stored permuted.
// ===========================================================================
__global__ __launch_bounds__(128) void eqc_kernel(const float* __restrict__ lin_w,
                                                  const float* __restrict__ lin_b,
                                                  int p) {
    const float* __restrict__ hq = g_h[p];
    const float* __restrict__ hc = g_h[p] + (size_t)BB * HH;
    const int n0 = blockIdx.x * 64;
    const int b0 = blockIdx.y * 64;

    __shared__ float As[16][65];
    __shared__ float Bs[16][65];

    const int tid = threadIdx.x;
    const int tx = tid & 15, ty = tid >> 4;

    float acc[8][4];
#pragma unroll
    for (int i = 0; i < 8; i++)
#pragma unroll
        for (int j = 0; j < 4; j++) acc[i][j] = 0.0f;

    for (int k0 = 0; k0 < HH; k0 += 16) {
#pragma unroll
        for (int l = 0; l < 8; l++) {
            int idx = tid + l * 128;
            int k = idx & 15, i = idx >> 4;
            size_t ga = (size_t)(b0 + i) * HH + (k0 + k);
            As[k][i] = 0.5f * (hq[ga] + hc[ga]);
            int ksrc = k0 + (k & ~7) + ip8(k & 7);       // inverse perm
            Bs[k][i] = lin_w[(size_t)(n0 + i) * HH + ksrc];
        }
        __syncthreads();
#pragma unroll
        for (int k = 0; k < 16; k++) {
            float a[8], b[4];
#pragma unroll
            for (int i = 0; i < 8; i++) a[i] = As[k][ty * 8 + i];
#pragma unroll
            for (int j = 0; j < 4; j++) b[j] = Bs[k][tx * 4 + j];
#pragma unroll
            for (int i = 0; i < 8; i++)
#pragma unroll
                for (int j = 0; j < 4; j++) acc[i][j] += a[i] * b[j];
        }
        __syncthreads();
    }

#pragma unroll
    for (int i = 0; i < 8; i++) {
        size_t rbase = (size_t)(b0 + ty * 8 + i) * HH;
#pragma unroll
        for (int j = 0; j < 4; j++) {
            int col = n0 + tx * 4 + j;
            int pp  = (col & ~7) | p8(col & 7);          // store permuted
            g_eqc[rbase + pp] = acc[i][j] + lin_b[col];
        }
    }
}

// ===========================================================================
// logits[m] = X_m @ er^T  (both operands K-permuted -> dot invariant)
// ===========================================================================
__global__ __launch_bounds__(128) void logits_kernel(float* __restrict__ out, int p) {
    const int m = blockIdx.z;
    const float* __restrict__ X  = (m == 0) ? g_h[p]
                                 : (m == 1) ? g_h[p] + (size_t)BB * HH
                                            : g_eqc;
    const float* __restrict__ er = g_h[p] + (size_t)2 * BB * HH;
    const int n0 = blockIdx.x * 64;
    const int b0 = blockIdx.y * 64;

    __shared__ float As[16][65];
    __shared__ float Bs[16][65];

    const int tid = threadIdx.x;
    const int tx = tid & 15, ty = tid >> 4;

    float acc[8][4];
#pragma unroll
    for (int i = 0; i < 8; i++)
#pragma unroll
        for (int j = 0; j < 4; j++) acc[i][j] = 0.0f;

    for (int k0 = 0; k0 < HH; k0 += 16) {
#pragma unroll
        for (int l = 0; l < 8; l++) {
            int idx = tid + l * 128;
            int k = idx & 15, i = idx >> 4;
            As[k][i] = X[(size_t)(b0 + i) * HH + (k0 + k)];
            Bs[k][i] = er[(size_t)(n0 + i) * HH + (k0 + k)];
        }
        __syncthreads();
#pragma unroll
        for (int k = 0; k < 16; k++) {
            float a[8], b[4];
#pragma unroll
            for (int i = 0; i < 8; i++) a[i] = As[k][ty * 8 + i];
#pragma unroll
            for (int j = 0; j < 4; j++) b[j] = Bs[k][tx * 4 + j];
#pragma unroll
            for (int i = 0; i < 8; i++)
#pragma unroll
                for (int j = 0; j < 4; j++) acc[i][j] += a[i] * b[j];
        }
        __syncthreads();
    }

#pragma unroll
    for (int i = 0; i < 8; i++) {
        size_t base = (size_t)m * BB * BB + (size_t)(b0 + ty * 8 + i) * BB + n0 + tx * 4;
#pragma unroll
        for (int j = 0; j < 4; j++) out[base + j] = acc[i][j];
    }
}

// ===========================================================================
// Row softmax over 3*B rows of length B, in-place on d_out.
// ===========================================================================
__global__ __launch_bounds__(256) void softmax_kernel(float* __restrict__ out) {
    float* prow = out + (size_t)blockIdx.x * BB;
    __shared__ float red[256];
    const int tid = threadIdx.x;

    float v[4];
    float mx = -1e30f;
#pragma unroll
    for (int l = 0; l < 4; l++) {
        v[l] = prow[tid + l * 256];
        mx = fmaxf(mx, v[l]);
    }
    red[tid] = mx;
    __syncthreads();
    for (int s = 128; s > 0; s >>= 1) {
        if (tid < s) red[tid] = fmaxf(red[tid], red[tid + s]);
        __syncthreads();
    }
    mx = red[0];
    __syncthreads();

    float sum = 0.0f;
#pragma unroll
    for (int l = 0; l < 4; l++) {
        v[l] = __expf(v[l] - mx);
        sum += v[l];
    }
    red[tid] = sum;
    __syncthreads();
    for (int s = 128; s > 0; s >>= 1) {
        if (tid < s) red[tid] += red[tid + s];
        __syncthreads();
    }
    float inv = 1.0f / red[0];
#pragma unroll
    for (int l = 0; l < 4; l++) prow[tid + l * 256] = v[l] * inv;
}

// ===========================================================================
// Launch
// ===========================================================================
extern "C" void kernel_launch(void* const* d_in, const int* in_sizes, int n_in,
                              void* d_out, int out_size) {
    (void)in_sizes; (void)n_in; (void)out_size;

    EncPack P;
    const int* toks[3] = { (const int*)d_in[0], (const int*)d_in[1], (const int*)d_in[2] };
    for (int e = 0; e < 3; e++) {
        int b = 3 + e * 5;
        P.e[e].tok = toks[e];
        P.e[e].emb = (const float*)d_in[b + 0];
        P.e[e].wih = (const float*)d_in[b + 1];
        P.e[e].whh = (const float*)d_in[b + 2];
        P.e[e].bih = (const float*)d_in[b + 3];
        P.e[e].bhh = (const float*)d_in[b + 4];
    }
    const float* lin_w = (const float*)d_in[18];
    const float* lin_b = (const float*)d_in[19];
    float* out = (float*)d_out;

    zero_h_kernel<<<(3 * BB * HH + 255) / 256, 256>>>();
    {
        size_t n = (size_t)3 * 16 * 128 * 640;
        pack_w_kernel<<<(unsigned)((n + 255) / 256), 256>>>(P);
    }
    {
        size_t n = (size_t)3 * VV * 128;
        pack_emb_kernel<<<(unsigned)((n + 255) / 256), 256>>>(P);
    }

    int p = 0;
    for (int t = SS - 1; t >= 0; --t) {
        step_tc_kernel<<<dim3(16, BB / 128, 3), 256>>>(P, t, p);
        p ^= 1;
    }

    eqc_kernel<<<dim3(HH / 64, BB / 64), 128>>>(lin_w, lin_b, p);
    logits_kernel<<<dim3(BB / 64, BB / 64, 3), 128>>>(out, p);
    softmax_kernel<<<3 * BB, 256>>>(out);
}

// round 8
// speedup vs baseline: 2.1675x; 1.3822x over previous
#include <cuda_runtime.h>
#include <cstdint>
#include <math.h>

#define BB 1024
#define SS 64
#define EE 100
#define HH 512
#define VV 50000

// ---------------------------------------------------------------------------
// Static device scratch (no allocations allowed)
// g_h: hidden state, values tf32-pre-rounded, K-PERMUTED within 8-groups.
// ---------------------------------------------------------------------------
__device__ float    g_h[2][3 * BB * HH];
__device__ float    g_eqc[BB * HH];
__device__ uint32_t g_wpk[(size_t)3 * 16 * 128 * 640];   // packed W panels, 15.7 MB
__device__ uint32_t g_embp[(size_t)3 * VV * 128];        // packed emb, 76.8 MB

struct Enc {
    const int*   tok;
    const float* emb;
    const float* wih;
    const float* whh;
    const float* bih;
    const float* bhh;
};
struct EncPack { Enc e[3]; };

__device__ __forceinline__ float sigmoidf_(float x) {
    return 1.0f / (1.0f + __expf(-x));
}

// ===========================================================================
// PTX helpers (sm_80-portable)
// ===========================================================================
__device__ __forceinline__ void cp16(uint32_t dst, const void* src) {
    asm volatile("cp.async.cg.shared.global [%0], [%1], 16;" :: "r"(dst), "l"(src));
}
#define CP_COMMIT() asm volatile("cp.async.commit_group;" ::: "memory")
#define CP_WAIT1()  asm volatile("cp.async.wait_group 1;" ::: "memory")

__device__ __forceinline__ uint32_t smem_u32(const void* p) {
    uint32_t a;
    asm("{ .reg .u64 t; cvta.to.shared.u64 t, %1; cvt.u32.u64 %0, t; }" : "=r"(a) : "l"(p));
    return a;
}
__device__ __forceinline__ uint32_t f2tf(float x) {
    uint32_t r;
    asm("cvt.rna.tf32.f32 %0, %1;" : "=r"(r) : "f"(x));
    return r;
}
__device__ __forceinline__ void mma8(float* d, const uint32_t* a, uint32_t b0, uint32_t b1) {
    asm volatile("mma.sync.aligned.m16n8k8.row.col.f32.tf32.tf32.f32 "
                 "{%0,%1,%2,%3}, {%4,%5,%6,%7}, {%8,%9}, {%0,%1,%2,%3};"
                 : "+f"(d[0]), "+f"(d[1]), "+f"(d[2]), "+f"(d[3])
                 : "r"(a[0]), "r"(a[1]), "r"(a[2]), "r"(a[3]), "r"(b0), "r"(b1));
}

// K-permutation within 8-groups: source k -> position 2*(k&3) + ((k>>2)&1)
// (positions (2j, 2j+1) hold source k = (j, j+4) -> mma frag pair is adjacent)
__device__ __forceinline__ int p8(int k)   { return ((k & 3) << 1) | ((k >> 2) & 1); }
// inverse: position p -> source k
__device__ __forceinline__ int ip8(int p)  { return ((p >> 1) & 3) | ((p & 1) << 2); }

// ===========================================================================
// Init + pack kernels
// ===========================================================================
__global__ void zero_h_kernel() {
    size_t i = (size_t)blockIdx.x * blockDim.x + threadIdx.x;
    if (i < (size_t)3 * BB * HH) g_h[0][i] = 0.0f;
}

// W panels: [e][jt(16)][n(128)][k(640), permuted].  n-tile nt=n>>3: jg=nt>>2,
// sec=nt&3, j=jt*32+jg*8+(n&7).  k<512: h-part (sec0..2=whh_r/z/n, sec3=0);
// k>=512: x-part kx=k-512 (sec0/1=wih_r/z, sec2=0, sec3=wih_n; kx>=100 -> 0).
__global__ void pack_w_kernel(EncPack P) {
    size_t id = (size_t)blockIdx.x * blockDim.x + threadIdx.x;
    if (id >= (size_t)3 * 16 * 128 * 640) return;
    int k  = (int)(id % 640);
    int n  = (int)((id / 640) % 128);
    int jt = (int)((id / (640 * 128)) % 16);
    int e  = (int)(id / (640 * 128 * 16));
    int nt = n >> 3, jg = nt >> 2, sec = nt & 3, jj = n & 7;
    int j = jt * 32 + jg * 8 + jj;
    float v = 0.0f;
    if (k < 512) {
        if (sec < 3) v = P.e[e].whh[(size_t)(sec * HH + j) * HH + k];
    } else {
        int kx = k - 512;
        if (kx < EE) {
            if (sec < 2)       v = P.e[e].wih[(size_t)(sec * HH + j) * EE + kx];
            else if (sec == 3) v = P.e[e].wih[(size_t)(2 * HH + j) * EE + kx];
        }
    }
    size_t dst = (((size_t)(e * 16 + jt) * 128 + n) * 640) + (k & ~7) + p8(k & 7);
    g_wpk[dst] = f2tf(v);
}

// emb: [e][v][k(128), permuted, zero-padded past E=100]
__global__ void pack_emb_kernel(EncPack P) {
    size_t id = (size_t)blockIdx.x * blockDim.x + threadIdx.x;
    if (id >= (size_t)3 * VV * 128) return;
    int k = (int)(id & 127);
    int v = (int)((id >> 7) % VV);
    int e = (int)(id / ((size_t)VV * 128));
    float x = (k < EE) ? P.e[e].emb[(size_t)v * EE + k] : 0.0f;
    g_embp[((size_t)e * VV + v) * 128 + (k & ~7) + p8(k & 7)] = f2tf(x);
}

// ===========================================================================
// Fused GRU step on tensor cores.  M=128 x N=128 x K=640 (20 chunks of 32).
// N sections per 8-j group: [r | z | h_n | i_n].  Inner loop: zero cvt,
// all fragment loads LDS.64, bank-conflict-free via uint4 XOR swizzle:
//   smem uint4 slot q -> q ^ ((row&3)<<1)   (row = 32-word row)
//   => fragment uint2 index u=(g*4+tg) lands at u' = ((g^(row&3))<<2)|tg,
//      16 distinct bank-pairs per 16-lane phase.
// grid (16, 8, 3), block 256 (warps 4m x 2n), 2 CTAs/SM, 66 KB dyn smem.
// ===========================================================================
#define NCHK 20
#define STGW (128 * 32)          // words per stage per operand

__global__ __launch_bounds__(256, 2) void step_tc_kernel(EncPack P, int t, int p) {
    extern __shared__ uint32_t dsm[];
    uint32_t* As = dsm;                       // [2][128*32]
    uint32_t* Bs = dsm + 2 * STGW;            // [2][128*32]
    int*      stok = (int*)(dsm + 4 * STGW);  // [128]

    const int e  = blockIdx.z;
    const Enc ep = P.e[e];
    const int jt = blockIdx.x;
    const int j0 = jt * 32;
    const int b0 = blockIdx.y * 128;

    const float* __restrict__ hin  = g_h[p]     + (size_t)e * BB * HH;
    float*       __restrict__ hout = g_h[p ^ 1] + (size_t)e * BB * HH;
    const uint32_t* __restrict__ Wp   = g_wpk  + ((size_t)(e * 16 + jt) * 128) * 640;
    const uint32_t* __restrict__ embp = g_embp + (size_t)e * VV * 128;

    const int tid = threadIdx.x;
    const int lane = tid & 31, wid = tid >> 5;
    const int gr = lane >> 2, tg = lane & 3;
    const int warp_m = wid & 3, warp_n = wid >> 2;
    const int xg = gr & 3;                    // xor term (row&3) for frag reads

    const uint32_t sA = smem_u32(As), sB = smem_u32(Bs);

    if (tid < 128) stok[tid] = ep.tok[(b0 + tid) * SS + t];
    __syncthreads();

    float acc[2][2][4][4];           // [mt][jg_l][sec][dreg]
#pragma unroll
    for (int a = 0; a < 2; a++)
#pragma unroll
        for (int b = 0; b < 2; b++)
#pragma unroll
            for (int s = 0; s < 4; s++)
#pragma unroll
                for (int c = 0; c < 4; c++) acc[a][b][s][c] = 0.0f;

    auto load_chunk = [&](int c, int st) {
        const uint32_t aB = sA + (uint32_t)st * STGW * 4;
        const uint32_t bB = sB + (uint32_t)st * STGW * 4;
#pragma unroll
        for (int it = 0; it < 4; it++) {
            int idx = tid + it * 256;            // [0,1024)
            int row = idx >> 3, kq = idx & 7;
            int q = kq ^ ((row & 3) << 1);       // swizzled uint4 slot
            uint32_t dof = (uint32_t)(row * 32 + q * 4) * 4;
            const void* asrc = (c < 16)
                ? (const void*)(hin + (size_t)(b0 + row) * HH + c * 32 + kq * 4)
                : (const void*)(embp + (size_t)stok[row] * 128 + (c - 16) * 32 + kq * 4);
            cp16(aB + dof, asrc);
            cp16(bB + dof, Wp + (size_t)row * 640 + c * 32 + kq * 4);
        }
    };

    load_chunk(0, 0);
    CP_COMMIT();

    for (int c = 0; c < NCHK; c++) {
        if (c + 1 < NCHK) load_chunk(c + 1, (c + 1) & 1);
        CP_COMMIT();
        CP_WAIT1();
        __syncthreads();
        const uint32_t* Ast = As + (c & 1) * STGW;
        const uint32_t* Bst = Bs + (c & 1) * STGW;
#pragma unroll
        for (int g = 0; g < 4; g++) {
            const int uw = (((g ^ xg) << 2) | tg) * 2;   // swizzled word offset
            uint32_t a[2][4];
#pragma unroll
            for (int mt = 0; mt < 2; mt++) {
                int rb = warp_m * 32 + mt * 16 + gr;
                uint2 lo = *(const uint2*)&Ast[rb * 32 + uw];
                uint2 hi = *(const uint2*)&Ast[(rb + 8) * 32 + uw];
                a[mt][0] = lo.x; a[mt][2] = lo.y; a[mt][1] = hi.x; a[mt][3] = hi.y;
            }
#pragma unroll
            for (int ntl = 0; ntl < 8; ntl++) {
                int n = warp_n * 64 + ntl * 8 + gr;
                uint2 bb = *(const uint2*)&Bst[n * 32 + uw];
                int jg_l = ntl >> 2, sec = ntl & 3;
                mma8(acc[0][jg_l][sec], a[0], bb.x, bb.y);
                mma8(acc[1][jg_l][sec], a[1], bb.x, bb.y);
            }
        }
        __syncthreads();
    }

    // ---- GRU epilogue (per-thread, in-register) ----
    float br[2][2], bz[2][2], bnh[2][2], bni[2][2];
    int   jp[2][2];
#pragma unroll
    for (int jg_l = 0; jg_l < 2; jg_l++)
#pragma unroll
        for (int cc = 0; cc < 2; cc++) {
            int j = j0 + (warp_n * 2 + jg_l) * 8 + tg * 2 + cc;
            br[jg_l][cc]  = ep.bih[j]          + ep.bhh[j];
            bz[jg_l][cc]  = ep.bih[HH + j]     + ep.bhh[HH + j];
            bnh[jg_l][cc] = ep.bhh[2 * HH + j];
            bni[jg_l][cc] = ep.bih[2 * HH + j];
            jp[jg_l][cc]  = (j & ~7) | p8(j & 7);      // permuted storage pos
        }

#pragma unroll
    for (int mt = 0; mt < 2; mt++) {
#pragma unroll
        for (int rp = 0; rp < 2; rp++) {
            const int row = b0 + warp_m * 32 + mt * 16 + gr + rp * 8;
            const float* hrow = hin + (size_t)row * HH;
            float*       orow = hout + (size_t)row * HH;
#pragma unroll
            for (int jg_l = 0; jg_l < 2; jg_l++) {
#pragma unroll
                for (int cc = 0; cc < 2; cc++) {
                    const int k = rp * 2 + cc;
                    float r = sigmoidf_(acc[mt][jg_l][0][k] + br[jg_l][cc]);
                    float z = sigmoidf_(acc[mt][jg_l][1][k] + bz[jg_l][cc]);
                    float n = tanhf(acc[mt][jg_l][3][k] + bni[jg_l][cc] +
                                    r * (acc[mt][jg_l][2][k] + bnh[jg_l][cc]));
                    float hv = (1.0f - z) * n + z * hrow[jp[jg_l][cc]];
                    orow[jp[jg_l][cc]] = __uint_as_float(f2tf(hv));
                }
            }
        }
    }
}

// ===========================================================================
// eqc = ((eq + ec) * 0.5) @ lin_w^T + lin_b.  h is K-permuted in storage:
// lin_w is read through the inverse permutation; output stored permuted.
// ===========================================================================
__global__ __launch_bounds__(128) void eqc_kernel(const float* __restrict__ lin_w,
                                                  const float* __restrict__ lin_b,
                                                  int p) {
    const float* __restrict__ hq = g_h[p];
    const float* __restrict__ hc = g_h[p] + (size_t)BB * HH;
    const int n0 = blockIdx.x * 64;
    const int b0 = blockIdx.y * 64;

    __shared__ float As[16][65];
    __shared__ float Bs[16][65];

    const int tid = threadIdx.x;
    const int tx = tid & 15, ty = tid >> 4;

    float acc[8][4];
#pragma unroll
    for (int i = 0; i < 8; i++)
#pragma unroll
        for (int j = 0; j < 4; j++) acc[i][j] = 0.0f;

    for (int k0 = 0; k0 < HH; k0 += 16) {
#pragma unroll
        for (int l = 0; l < 8; l++) {
            int idx = tid + l * 128;
            int k = idx & 15, i = idx >> 4;
            size_t ga = (size_t)(b0 + i) * HH + (k0 + k);
            As[k][i] = 0.5f * (hq[ga] + hc[ga]);
            int ksrc = k0 + (k & ~7) + ip8(k & 7);       // inverse perm
            Bs[k][i] = lin_w[(size_t)(n0 + i) * HH + ksrc];
        }
        __syncthreads();
#pragma unroll
        for (int k = 0; k < 16; k++) {
            float a[8], b[4];
#pragma unroll
            for (int i = 0; i < 8; i++) a[i] = As[k][ty * 8 + i];
#pragma unroll
            for (int j = 0; j < 4; j++) b[j] = Bs[k][tx * 4 + j];
#pragma unroll
            for (int i = 0; i < 8; i++)
#pragma unroll
                for (int j = 0; j < 4; j++) acc[i][j] += a[i] * b[j];
        }
        __syncthreads();
    }

#pragma unroll
    for (int i = 0; i < 8; i++) {
        size_t rbase = (size_t)(b0 + ty * 8 + i) * HH;
#pragma unroll
        for (int j = 0; j < 4; j++) {
            int col = n0 + tx * 4 + j;
            int pp  = (col & ~7) | p8(col & 7);          // store permuted
            g_eqc[rbase + pp] = acc[i][j] + lin_b[col];
        }
    }
}

// ===========================================================================
// logits[m] = X_m @ er^T  (both operands K-permuted -> dot invariant)
// ===========================================================================
__global__ __launch_bounds__(128) void logits_kernel(float* __restrict__ out, int p) {
    const int m = blockIdx.z;
    const float* __restrict__ X  = (m == 0) ? g_h[p]
                                 : (m == 1) ? g_h[p] + (size_t)BB * HH
                                            : g_eqc;
    const float* __restrict__ er = g_h[p] + (size_t)2 * BB * HH;
    const int n0 = blockIdx.x * 64;
    const int b0 = blockIdx.y * 64;

    __shared__ float As[16][65];
    __shared__ float Bs[16][65];

    const int tid = threadIdx.x;
    const int tx = tid & 15, ty = tid >> 4;

    float acc[8][4];
#pragma unroll
    for (int i = 0; i < 8; i++)
#pragma unroll
        for (int j = 0; j < 4; j++) acc[i][j] = 0.0f;

    for (int k0 = 0; k0 < HH; k0 += 16) {
#pragma unroll
        for (int l = 0; l < 8; l++) {
            int idx = tid + l * 128;
            int k = idx & 15, i = idx >> 4;
            As[k][i] = X[(size_t)(b0 + i) * HH + (k0 + k)];
            Bs[k][i] = er[(size_t)(n0 + i) * HH + (k0 + k)];
        }
        __syncthreads();
#pragma unroll
        for (int k = 0; k < 16; k++) {
            float a[8], b[4];
#pragma unroll
            for (int i = 0; i < 8; i++) a[i] = As[k][ty * 8 + i];
#pragma unroll
            for (int j = 0; j < 4; j++) b[j] = Bs[k][tx * 4 + j];
#pragma unroll
            for (int i = 0; i < 8; i++)
#pragma unroll
                for (int j = 0; j < 4; j++) acc[i][j] += a[i] * b[j];
        }
        __syncthreads();
    }

#pragma unroll
    for (int i = 0; i < 8; i++) {
        size_t base = (size_t)m * BB * BB + (size_t)(b0 + ty * 8 + i) * BB + n0 + tx * 4;
#pragma unroll
        for (int j = 0; j < 4; j++) out[base + j] = acc[i][j];
    }
}

// ===========================================================================
// Row softmax over 3*B rows of length B, in-place on d_out.
// ===========================================================================
__global__ __launch_bounds__(256) void softmax_kernel(float* __restrict__ out) {
    float* prow = out + (size_t)blockIdx.x * BB;
    __shared__ float red[256];
    const int tid = threadIdx.x;

    float v[4];
    float mx = -1e30f;
#pragma unroll
    for (int l = 0; l < 4; l++) {
        v[l] = prow[tid + l * 256];
        mx = fmaxf(mx, v[l]);
    }
    red[tid] = mx;
    __syncthreads();
    for (int s = 128; s > 0; s >>= 1) {
        if (tid < s) red[tid] = fmaxf(red[tid], red[tid + s]);
        __syncthreads();
    }
    mx = red[0];
    __syncthreads();

    float sum = 0.0f;
#pragma unroll
    for (int l = 0; l < 4; l++) {
        v[l] = __expf(v[l] - mx);
        sum += v[l];
    }
    red[tid] = sum;
    __syncthreads();
    for (int s = 128; s > 0; s >>= 1) {
        if (tid < s) red[tid] += red[tid + s];
        __syncthreads();
    }
    float inv = 1.0f / red[0];
#pragma unroll
    for (int l = 0; l < 4; l++) prow[tid + l * 256] = v[l] * inv;
}

// ===========================================================================
// Launch
// ===========================================================================
extern "C" void kernel_launch(void* const* d_in, const int* in_sizes, int n_in,
                              void* d_out, int out_size) {
    (void)in_sizes; (void)n_in; (void)out_size;

    EncPack P;
    const int* toks[3] = { (const int*)d_in[0], (const int*)d_in[1], (const int*)d_in[2] };
    for (int e = 0; e < 3; e++) {
        int b = 3 + e * 5;
        P.e[e].tok = toks[e];
        P.e[e].emb = (const float*)d_in[b + 0];
        P.e[e].wih = (const float*)d_in[b + 1];
        P.e[e].whh = (const float*)d_in[b + 2];
        P.e[e].bih = (const float*)d_in[b + 3];
        P.e[e].bhh = (const float*)d_in[b + 4];
    }
    const float* lin_w = (const float*)d_in[18];
    const float* lin_b = (const float*)d_in[19];
    float* out = (float*)d_out;

    const int SMEM_DYN = (4 * STGW) * 4 + 128 * 4;   // 66048 B
    cudaFuncSetAttribute(step_tc_kernel,
                         cudaFuncAttributeMaxDynamicSharedMemorySize, SMEM_DYN);

    zero_h_kernel<<<(3 * BB * HH + 255) / 256, 256>>>();
    {
        size_t n = (size_t)3 * 16 * 128 * 640;
        pack_w_kernel<<<(unsigned)((n + 255) / 256), 256>>>(P);
    }
    {
        size_t n = (size_t)3 * VV * 128;
        pack_emb_kernel<<<(unsigned)((n + 255) / 256), 256>>>(P);
    }

    int p = 0;
    for (int t = SS - 1; t >= 0; --t) {
        step_tc_kernel<<<dim3(16, BB / 128, 3), 256, SMEM_DYN>>>(P, t, p);
        p ^= 1;
    }

    eqc_kernel<<<dim3(HH / 64, BB / 64), 128>>>(lin_w, lin_b, p);
    logits_kernel<<<dim3(BB / 64, BB / 64, 3), 128>>>(out, p);
    softmax_kernel<<<3 * BB, 256>>>(out);
}

// round 12
// speedup vs baseline: 3.4995x; 1.6145x over previous
#include <cuda_runtime.h>
#include <cuda_fp16.h>
#include <cstdint>
#include <math.h>

#define BB 1024
#define SS 64
#define EE 100
#define HH 512
#define VV 50000

// ---------------------------------------------------------------------------
// Static device scratch (no allocations allowed)
// g_h:   fp32 hidden, NATURAL order (blend path + tail kernels)
// g_hhf: fp16 hidden, K-PERMUTED within 16-groups (GEMM A path)
// ---------------------------------------------------------------------------
__device__ float    g_h[2][3 * BB * HH];
__device__ __half   g_hhf[2][3 * BB * HH];
__device__ float    g_eqc[BB * HH];
__device__ __half   g_wpk[(size_t)3 * 16 * 128 * 640];  // packed W, 7.9 MB
__device__ __half   g_embp[(size_t)3 * VV * 128];       // packed emb, 38.4 MB

struct Enc {
    const int*   tok;
    const float* emb;
    const float* wih;
    const float* whh;
    const float* bih;
    const float* bhh;
};
struct EncPack { Enc e[3]; };

__device__ __forceinline__ float sigmoidf_(float x) {
    return 1.0f / (1.0f + __expf(-x));
}

// ===========================================================================
// PTX helpers (sm_80-portable)
// ===========================================================================
__device__ __forceinline__ void cp16(uint32_t dst, const void* src) {
    asm volatile("cp.async.cg.shared.global [%0], [%1], 16;" :: "r"(dst), "l"(src));
}
#define CP_COMMIT() asm volatile("cp.async.commit_group;" ::: "memory")
#define CP_WAIT1()  asm volatile("cp.async.wait_group 1;" ::: "memory")

__device__ __forceinline__ uint32_t smem_u32(const void* p) {
    uint32_t a;
    asm("{ .reg .u64 t; cvta.to.shared.u64 t, %1; cvt.u32.u64 %0, t; }" : "=r"(a) : "l"(p));
    return a;
}
__device__ __forceinline__ void mma16(float* d, const uint32_t* a, uint32_t b0, uint32_t b1) {
    asm volatile("mma.sync.aligned.m16n8k16.row.col.f32.f16.f16.f32 "
                 "{%0,%1,%2,%3}, {%4,%5,%6,%7}, {%8,%9}, {%0,%1,%2,%3};"
                 : "+f"(d[0]), "+f"(d[1]), "+f"(d[2]), "+f"(d[3])
                 : "r"(a[0]), "r"(a[1]), "r"(a[2]), "r"(a[3]), "r"(b0), "r"(b1));
}

// K-permutation within 16-groups for m16n8k16 frags:
// source k -> position 4*((k>>1)&3) + (k&1) + 2*((k>>3)&1)
// => thread tg's halves {2tg, 2tg+1, 2tg+8, 2tg+9} land at positions 4tg..4tg+3.
__device__ __forceinline__ int p16(int k) {
    return (((k >> 1) & 3) << 2) | (k & 1) | (((k >> 3) & 1) << 1);
}

// ===========================================================================
// Init + pack kernels
// ===========================================================================
__global__ void zero_h_kernel() {
    size_t i = (size_t)blockIdx.x * blockDim.x + threadIdx.x;
    if (i < (size_t)3 * BB * HH) {
        g_h[0][i]   = 0.0f;
        g_hhf[0][i] = __float2half_rn(0.0f);
    }
}

// W panels: [e][jt(16)][n(128)][k(640), p16-permuted].  n-tile nt=n>>3: jg=nt>>2,
// sec=nt&3, j=jt*32+jg*8+(n&7).  k<512: h-part (sec0..2=whh_r/z/n, sec3=0);
// k>=512: kx=k-512 (sec0/1=wih_r/z, sec2=0, sec3=wih_n; kx>=100 -> 0).
__global__ void pack_w_kernel(EncPack P) {
    size_t id = (size_t)blockIdx.x * blockDim.x + threadIdx.x;
    if (id >= (size_t)3 * 16 * 128 * 640) return;
    int k  = (int)(id % 640);
    int n  = (int)((id / 640) % 128);
    int jt = (int)((id / (640 * 128)) % 16);
    int e  = (int)(id / (640 * 128 * 16));
    int nt = n >> 3, jg = nt >> 2, sec = nt & 3, jj = n & 7;
    int j = jt * 32 + jg * 8 + jj;
    float v = 0.0f;
    if (k < 512) {
        if (sec < 3) v = P.e[e].whh[(size_t)(sec * HH + j) * HH + k];
    } else {
        int kx = k - 512;
        if (kx < EE) {
            if (sec < 2)       v = P.e[e].wih[(size_t)(sec * HH + j) * EE + kx];
            else if (sec == 3) v = P.e[e].wih[(size_t)(2 * HH + j) * EE + kx];
        }
    }
    size_t dst = (((size_t)(e * 16 + jt) * 128 + n) * 640) + (k & ~15) + p16(k & 15);
    g_wpk[dst] = __float2half_rn(v);
}

// emb: [e][v][k(128), p16-permuted, zero-padded past E=100]
__global__ void pack_emb_kernel(EncPack P) {
    size_t id = (size_t)blockIdx.x * blockDim.x + threadIdx.x;
    if (id >= (size_t)3 * VV * 128) return;
    int k = (int)(id & 127);
    int v = (int)((id >> 7) % VV);
    int e = (int)(id / ((size_t)VV * 128));
    float x = (k < EE) ? P.e[e].emb[(size_t)v * EE + k] : 0.0f;
    g_embp[((size_t)e * VV + v) * 128 + (k & ~15) + p16(k & 15)] = __float2half_rn(x);
}

// ===========================================================================
// Fused GRU step, fp16 m16n8k16 (fp32 accum).  M=128 x N=128 x K=640
// (10 chunks of 64).  N sections per 8-j group: [r | z | h_n | i_n].
// smem rows: 128 fp16 (128B = 32 words = 8 uint4 slots), XOR swizzle
//   uint4 slot q -> q ^ ((row&3)<<1); frag reader uses the SAME xor term
//   (xg<<1) -> loader/reader consistent, conflict-free LDS.64.
// grid (16, 8, 3), block 256 (warps 4m x 2n), 2 CTAs/SM, 64.5 KB dyn smem.
// ===========================================================================
#define NCHK 10
#define STGW (128 * 32)          // uint32 words per stage per operand

__global__ __launch_bounds__(256, 2) void step_tc_kernel(EncPack P, int t, int p) {
    extern __shared__ uint32_t dsm[];
    uint32_t* As = dsm;                       // [2][STGW]
    uint32_t* Bs = dsm + 2 * STGW;            // [2][STGW]
    int*      stok = (int*)(dsm + 4 * STGW);  // [128]

    const int e  = blockIdx.z;
    const Enc ep = P.e[e];
    const int jt = blockIdx.x;
    const int j0 = jt * 32;
    const int b0 = blockIdx.y * 128;

    const float* __restrict__ hin  = g_h[p]     + (size_t)e * BB * HH;
    float*       __restrict__ hout = g_h[p ^ 1] + (size_t)e * BB * HH;
    const __half* __restrict__ hhf  = g_hhf[p]     + (size_t)e * BB * HH;
    __half*       __restrict__ hhfo = g_hhf[p ^ 1] + (size_t)e * BB * HH;
    const __half* __restrict__ Wp   = g_wpk  + ((size_t)(e * 16 + jt) * 128) * 640;
    const __half* __restrict__ embp = g_embp + (size_t)e * VV * 128;

    const int tid = threadIdx.x;
    const int lane = tid & 31, wid = tid >> 5;
    const int gr = lane >> 2, tg = lane & 3;
    const int warp_m = wid & 3, warp_n = wid >> 2;
    const int xg = gr & 3;                    // row&3 of every row this thread reads

    const uint32_t sA = smem_u32(As), sB = smem_u32(Bs);

    if (tid < 128) stok[tid] = ep.tok[(b0 + tid) * SS + t];
    __syncthreads();

    // Per-thread swizzled word offsets for the 4 k16-iterations of a chunk.
    // Unswizzled word w = 8g + 2tg; slot = (w>>2) ^ (xg<<1)  [matches loader];
    // woff = slot*4 + (w&3).
    int woff[4];
#pragma unroll
    for (int g = 0; g < 4; g++) {
        int w = 8 * g + 2 * tg;
        woff[g] = (((w >> 2) ^ (xg << 1)) << 2) | (w & 3);
    }

    float acc[2][2][4][4];           // [mt][jg_l][sec][dreg]
#pragma unroll
    for (int a = 0; a < 2; a++)
#pragma unroll
        for (int b = 0; b < 2; b++)
#pragma unroll
            for (int s = 0; s < 4; s++)
#pragma unroll
                for (int c = 0; c < 4; c++) acc[a][b][s][c] = 0.0f;

    auto load_chunk = [&](int c, int st) {
        const uint32_t aB = sA + (uint32_t)st * STGW * 4;
        const uint32_t bB = sB + (uint32_t)st * STGW * 4;
#pragma unroll
        for (int it = 0; it < 4; it++) {
            int idx = tid + it * 256;            // [0,1024): row 0..127, kq 0..7
            int row = idx >> 3, kq = idx & 7;
            int q = kq ^ ((row & 3) << 1);       // swizzled uint4 slot
            uint32_t dof = (uint32_t)(row * 32 + q * 4) * 4;
            const void* asrc = (c < 8)
                ? (const void*)(hhf + (size_t)(b0 + row) * HH + c * 64 + kq * 8)
                : (const void*)(embp + (size_t)stok[row] * 128 + (c - 8) * 64 + kq * 8);
            cp16(aB + dof, asrc);
            cp16(bB + dof, Wp + (size_t)row * 640 + c * 64 + kq * 8);
        }
    };

    load_chunk(0, 0);
    CP_COMMIT();

    for (int c = 0; c < NCHK; c++) {
        if (c + 1 < NCHK) load_chunk(c + 1, (c + 1) & 1);
        CP_COMMIT();
        CP_WAIT1();
        __syncthreads();
        const uint32_t* Ast = As + (c & 1) * STGW;
        const uint32_t* Bst = Bs + (c & 1) * STGW;
#pragma unroll
        for (int g = 0; g < 4; g++) {
            const int uw = woff[g];
            uint32_t a[2][4];
#pragma unroll
            for (int mt = 0; mt < 2; mt++) {
                int rb = warp_m * 32 + mt * 16 + gr;
                uint2 lo = *(const uint2*)&Ast[rb * 32 + uw];
                uint2 hi = *(const uint2*)&Ast[(rb + 8) * 32 + uw];
                a[mt][0] = lo.x; a[mt][2] = lo.y; a[mt][1] = hi.x; a[mt][3] = hi.y;
            }
#pragma unroll
            for (int ntl = 0; ntl < 8; ntl++) {
                int n = warp_n * 64 + ntl * 8 + gr;
                uint2 bb = *(const uint2*)&Bst[n * 32 + uw];
                int jg_l = ntl >> 2, sec = ntl & 3;
                mma16(acc[0][jg_l][sec], a[0], bb.x, bb.y);
                mma16(acc[1][jg_l][sec], a[1], bb.x, bb.y);
            }
        }
        __syncthreads();
    }

    // ---- GRU epilogue (per-thread, in-register) ----
    float br[2][2], bz[2][2], bnh[2][2], bni[2][2];
    int   jp[2][2];
#pragma unroll
    for (int jg_l = 0; jg_l < 2; jg_l++)
#pragma unroll
        for (int cc = 0; cc < 2; cc++) {
            int j = j0 + (warp_n * 2 + jg_l) * 8 + tg * 2 + cc;
            br[jg_l][cc]  = ep.bih[j]          + ep.bhh[j];
            bz[jg_l][cc]  = ep.bih[HH + j]     + ep.bhh[HH + j];
            bnh[jg_l][cc] = ep.bhh[2 * HH + j];
            bni[jg_l][cc] = ep.bih[2 * HH + j];
            jp[jg_l][cc]  = (j & ~15) | p16(j & 15);   // fp16 permuted pos
        }

#pragma unroll
    for (int mt = 0; mt < 2; mt++) {
#pragma unroll
        for (int rp = 0; rp < 2; rp++) {
            const int row = b0 + warp_m * 32 + mt * 16 + gr + rp * 8;
            const float* hrow = hin + (size_t)row * HH;
            float*       orow = hout + (size_t)row * HH;
            __half*      ohrow = hhfo + (size_t)row * HH;
#pragma unroll
            for (int jg_l = 0; jg_l < 2; jg_l++) {
#pragma unroll
                for (int cc = 0; cc < 2; cc++) {
                    const int j = j0 + (warp_n * 2 + jg_l) * 8 + tg * 2 + cc;
                    const int k = rp * 2 + cc;
                    float r = sigmoidf_(acc[mt][jg_l][0][k] + br[jg_l][cc]);
                    float z = sigmoidf_(acc[mt][jg_l][1][k] + bz[jg_l][cc]);
                    float n = tanhf(acc[mt][jg_l][3][k] + bni[jg_l][cc] +
                                    r * (acc[mt][jg_l][2][k] + bnh[jg_l][cc]));
                    float hv = (1.0f - z) * n + z * hrow[j];
                    orow[j] = hv;                              // fp32 master
                    ohrow[jp[jg_l][cc]] = __float2half_rn(hv); // fp16 GEMM copy
                }
            }
        }
    }
}

// ===========================================================================
// eqc = ((eq + ec) * 0.5) @ lin_w^T + lin_b   (natural-order fp32 h)
// ===========================================================================
__global__ __launch_bounds__(128) void eqc_kernel(const float* __restrict__ lin_w,
                                                  const float* __restrict__ lin_b,
                                                  int p) {
    const float* __restrict__ hq = g_h[p];
    const float* __restrict__ hc = g_h[p] + (size_t)BB * HH;
    const int n0 = blockIdx.x * 64;
    const int b0 = blockIdx.y * 64;

    __shared__ float As[16][65];
    __shared__ float Bs[16][65];

    const int tid = threadIdx.x;
    const int tx = tid & 15, ty = tid >> 4;

    float acc[8][4];
#pragma unroll
    for (int i = 0; i < 8; i++)
#pragma unroll
        for (int j = 0; j < 4; j++) acc[i][j] = 0.0f;

    for (int k0 = 0; k0 < HH; k0 += 16) {
#pragma unroll
        for (int l = 0; l < 8; l++) {
            int idx = tid + l * 128;
            int k = idx & 15, i = idx >> 4;
            size_t ga = (size_t)(b0 + i) * HH + (k0 + k);
            As[k][i] = 0.5f * (hq[ga] + hc[ga]);
            Bs[k][i] = lin_w[(size_t)(n0 + i) * HH + (k0 + k)];
        }
        __syncthreads();
#pragma unroll
        for (int k = 0; k < 16; k++) {
            float a[8], b[4];
#pragma unroll
            for (int i = 0; i < 8; i++) a[i] = As[k][ty * 8 + i];
#pragma unroll
            for (int j = 0; j < 4; j++) b[j] = Bs[k][tx * 4 + j];
#pragma unroll
            for (int i = 0; i < 8; i++)
#pragma unroll
                for (int j = 0; j < 4; j++) acc[i][j] += a[i] * b[j];
        }
        __syncthreads();
    }

    float bi[4];
#pragma unroll
    for (int j = 0; j < 4; j++) bi[j] = lin_b[n0 + tx * 4 + j];
#pragma unroll
    for (int i = 0; i < 8; i++) {
        size_t base = (size_t)(b0 + ty * 8 + i) * HH + n0 + tx * 4;
#pragma unroll
        for (int j = 0; j < 4; j++) g_eqc[base + j] = acc[i][j] + bi[j];
    }
}

// ===========================================================================
// logits[m] = X_m @ er^T, writes d_out
// ===========================================================================
__global__ __launch_bounds__(128) void logits_kernel(float* __restrict__ out, int p) {
    const int m = blockIdx.z;
    const float* __restrict__ X  = (m == 0) ? g_h[p]
                                 : (m == 1) ? g_h[p] + (size_t)BB * HH
                                            : g_eqc;
    const float* __restrict__ er = g_h[p] + (size_t)2 * BB * HH;
    const int n0 = blockIdx.x * 64;
    const int b0 = blockIdx.y * 64;

    __shared__ float As[16][65];
    __shared__ float Bs[16][65];

    const int tid = threadIdx.x;
    const int tx = tid & 15, ty = tid >> 4;

    float acc[8][4];
#pragma unroll
    for (int i = 0; i < 8; i++)
#pragma unroll
        for (int j = 0; j < 4; j++) acc[i][j] = 0.0f;

    for (int k0 = 0; k0 < HH; k0 += 16) {
#pragma unroll
        for (int l = 0; l < 8; l++) {
            int idx = tid + l * 128;
            int k = idx & 15, i = idx >> 4;
            As[k][i] = X[(size_t)(b0 + i) * HH + (k0 + k)];
            Bs[k][i] = er[(size_t)(n0 + i) * HH + (k0 + k)];
        }
        __syncthreads();
#pragma unroll
        for (int k = 0; k < 16; k++) {
            float a[8], b[4];
#pragma unroll
            for (int i = 0; i < 8; i++) a[i] = As[k][ty * 8 + i];
#pragma unroll
            for (int j = 0; j < 4; j++) b[j] = Bs[k][tx * 4 + j];
#pragma unroll
            for (int i = 0; i < 8; i++)
#pragma unroll
                for (int j = 0; j < 4; j++) acc[i][j] += a[i] * b[j];
        }
        __syncthreads();
    }

#pragma unroll
    for (int i = 0; i < 8; i++) {
        size_t base = (size_t)m * BB * BB + (size_t)(b0 + ty * 8 + i) * BB + n0 + tx * 4;
#pragma unroll
        for (int j = 0; j < 4; j++) out[base + j] = acc[i][j];
    }
}

// ===========================================================================
// Row softmax over 3*B rows of length B, in-place on d_out.
// ===========================================================================
__global__ __launch_bounds__(256) void softmax_kernel(float* __restrict__ out) {
    float* prow = out + (size_t)blockIdx.x * BB;
    __shared__ float red[256];
    const int tid = threadIdx.x;

    float v[4];
    float mx = -1e30f;
#pragma unroll
    for (int l = 0; l < 4; l++) {
        v[l] = prow[tid + l * 256];
        mx = fmaxf(mx, v[l]);
    }
    red[tid] = mx;
    __syncthreads();
    for (int s = 128; s > 0; s >>= 1) {
        if (tid < s) red[tid] = fmaxf(red[tid], red[tid + s]);
        __syncthreads();
    }
    mx = red[0];
    __syncthreads();

    float sum = 0.0f;
#pragma unroll
    for (int l = 0; l < 4; l++) {
        v[l] = __expf(v[l] - mx);
        sum += v[l];
    }
    red[tid] = sum;
    __syncthreads();
    for (int s = 128; s > 0; s >>= 1) {
        if (tid < s) red[tid] += red[tid + s];
        __syncthreads();
    }
    float inv = 1.0f / red[0];
#pragma unroll
    for (int l = 0; l < 4; l++) prow[tid + l * 256] = v[l] * inv;
}

// ===========================================================================
// Launch
// ===========================================================================
extern "C" void kernel_launch(void* const* d_in, const int* in_sizes, int n_in,
                              void* d_out, int out_size) {
    (void)in_sizes; (void)n_in; (void)out_size;

    EncPack P;
    const int* toks[3] = { (const int*)d_in[0], (const int*)d_in[1], (const int*)d_in[2] };
    for (int e = 0; e < 3; e++) {
        int b = 3 + e * 5;
        P.e[e].tok = toks[e];
        P.e[e].emb = (const float*)d_in[b + 0];
        P.e[e].wih = (const float*)d_in[b + 1];
        P.e[e].whh = (const float*)d_in[b + 2];
        P.e[e].bih = (const float*)d_in[b + 3];
        P.e[e].bhh = (const float*)d_in[b + 4];
    }
    const float* lin_w = (const float*)d_in[18];
    const float* lin_b = (const float*)d_in[19];
    float* out = (float*)d_out;

    const int SMEM_DYN = (4 * STGW) * 4 + 128 * 4;   // 66048 B
    cudaFuncSetAttribute(step_tc_kernel,
                         cudaFuncAttributeMaxDynamicSharedMemorySize, SMEM_DYN);

    zero_h_kernel<<<(3 * BB * HH + 255) / 256, 256>>>();
    {
        size_t n = (size_t)3 * 16 * 128 * 640;
        pack_w_kernel<<<(unsigned)((n + 255) / 256), 256>>>(P);
    }
    {
        size_t n = (size_t)3 * VV * 128;
        pack_emb_kernel<<<(unsigned)((n + 255) / 256), 256>>>(P);
    }

    int p = 0;
    for (int t = SS - 1; t >= 0; --t) {
        step_tc_kernel<<<dim3(16, BB / 128, 3), 256, SMEM_DYN>>>(P, t, p);
        p ^= 1;
    }

    eqc_kernel<<<dim3(HH / 64, BB / 64), 128>>>(lin_w, lin_b, p);
    logits_kernel<<<dim3(BB / 64, BB / 64, 3), 128>>>(out, p);
    softmax_kernel<<<3 * BB, 256>>>(out);
}